// round 2
// baseline (speedup 1.0000x reference)
#include <cuda_runtime.h>
#include <math.h>

#define T_STEPS 256
#define LLEN    1024
#define CIN     14
#define CCONV   32
#define H       128
#define G4H     512
#define NC      7
#define M_TOT   (T_STEPS*LLEN)   // 262144

// ---------------- scratch (device globals; allocation is banned) ----------
__device__ float g_cur1[(size_t)M_TOT * CCONV];   //  32 MB  conv spikes [row, 32]
__device__ float g_xproj[(size_t)M_TOT * G4H];    // 512 MB  x-projection, reused by both layers
__device__ float g_spk1[(size_t)M_TOT * H];       // 128 MB  layer-1 spikes [row, H]
__device__ float g_synA[LLEN * H];
__device__ float g_memA[LLEN * H];                // double-buffered membrane
__device__ float g_memB[LLEN * H];
__device__ float g_memsum[LLEN * H];
__device__ float g_part[256 * H];                 // BN partial sums
__device__ float g_whh1T[H * G4H];                // w_hh1 transposed [k][j]
__device__ float g_whh2T[H * G4H];
__device__ float g_wih1T[CCONV * G4H];            // w_ih1 transposed [k][j]
__device__ float g_awT[H * G4H];                  // BN-scaled w_ih2 transposed
__device__ float g_bias1[G4H];                    // b_ih1 + b_hh1
__device__ float g_bias2[G4H];                    // b_ih2 + b_hh2 + BN-shift folded

// ---------------- prep: weight transposes + bias combine -------------------
__global__ void prep0(const float* __restrict__ w_ih1, const float* __restrict__ w_hh1,
                      const float* __restrict__ b_ih1, const float* __restrict__ b_hh1,
                      const float* __restrict__ w_hh2) {
    int stride = gridDim.x * blockDim.x;
    int i0 = blockIdx.x * blockDim.x + threadIdx.x;
    for (int idx = i0; idx < H * G4H; idx += stride) {
        int k = idx / G4H, j = idx % G4H;
        g_whh1T[idx] = w_hh1[j * H + k];
        g_whh2T[idx] = w_hh2[j * H + k];
    }
    for (int idx = i0; idx < CCONV * G4H; idx += stride) {
        int k = idx / G4H, j = idx % G4H;
        g_wih1T[idx] = w_ih1[j * CCONV + k];
    }
    for (int idx = i0; idx < G4H; idx += stride)
        g_bias1[idx] = b_ih1[idx] + b_hh1[idx];
}

// ---------------- zero state -----------------------------------------------
__global__ void zero_state() {
    int i = blockIdx.x * blockDim.x + threadIdx.x;
    if (i < LLEN * H) {
        g_synA[i] = 0.f; g_memA[i] = 0.f; g_memB[i] = 0.f; g_memsum[i] = 0.f;
    }
}

// ---------------- conv1d(k=3,pad=1) + Leaky spike ---------------------------
__global__ void __launch_bounds__(256) conv_spike(const float* __restrict__ x,
                                                  const float* __restrict__ conv_w,
                                                  const float* __restrict__ conv_b) {
    __shared__ float sw[3][CIN][CCONV];
    __shared__ float sb[CCONV];
    int tid = threadIdx.x;
    for (int i = tid; i < 3 * CIN * CCONV; i += 256) {
        int c = i % CCONV; int rem = i / CCONV; int ci = rem % CIN; int kk = rem / CIN;
        sw[kk][ci][c] = conv_w[(c * CIN + ci) * 3 + kk];
    }
    if (tid < CCONV) sb[tid] = conv_b[tid];
    __syncthreads();

    int gid = blockIdx.x * 256 + tid;   // over M_TOT
    int t = gid >> 10, l = gid & 1023;
    float acc[CCONV];
#pragma unroll
    for (int c = 0; c < CCONV; c++) acc[c] = sb[c];
#pragma unroll
    for (int kk = 0; kk < 3; kk++) {
        int ll = l + kk - 1;
        bool valid = (ll >= 0 && ll < LLEN);
        const float* xp = x + ((size_t)t * LLEN + (valid ? ll : 0)) * CIN;
#pragma unroll
        for (int ci = 0; ci < CIN; ci++) {
            float xv = valid ? xp[ci] : 0.f;
#pragma unroll
            for (int c = 0; c < CCONV; c++) acc[c] = fmaf(xv, sw[kk][ci][c], acc[c]);
        }
    }
    float4* outp = (float4*)&g_cur1[(size_t)gid * CCONV];
#pragma unroll
    for (int q = 0; q < 8; q++) {
        float4 v;
        v.x = (acc[q*4+0] - 1.0f) > 0.f ? 1.f : 0.f;
        v.y = (acc[q*4+1] - 1.0f) > 0.f ? 1.f : 0.f;
        v.z = (acc[q*4+2] - 1.0f) > 0.f ? 1.f : 0.f;
        v.w = (acc[q*4+3] - 1.0f) > 0.f ? 1.f : 0.f;
        outp[q] = v;
    }
}

// ---------------- hoisted x-projection GEMM: out = in @ wT + bias ----------
// SRC==0 : in = g_cur1 (K=32),  wT = g_wih1T, bias = g_bias1
// SRC==1 : in = g_spk1 (K=128), wT = g_awT,   bias = g_bias2
template<int K, int SRC>
__global__ void __launch_bounds__(256) gemm_xproj() {
    __shared__ float sIn[K][16];
    const float* __restrict__ in   = (SRC == 0) ? g_cur1  : g_spk1;
    const float* __restrict__ wT   = (SRC == 0) ? g_wih1T : g_awT;
    const float* __restrict__ bias = (SRC == 0) ? g_bias1 : g_bias2;
    int tid = threadIdx.x;
    int row0 = blockIdx.x << 4;
    for (int idx = tid; idx < 16 * K; idx += 256) {
        int r = idx / K, k = idx % K;
        sIn[k][r] = in[(size_t)(row0 + r) * K + k];
    }
    __syncthreads();
    int j0 = tid, j1 = tid + 256;
    float acc0[16], acc1[16];
#pragma unroll
    for (int r = 0; r < 16; r++) { acc0[r] = 0.f; acc1[r] = 0.f; }
#pragma unroll 8
    for (int k = 0; k < K; k++) {
        float w0 = wT[k * G4H + j0];
        float w1 = wT[k * G4H + j1];
        float4 m0 = *(const float4*)&sIn[k][0];
        float4 m1 = *(const float4*)&sIn[k][4];
        float4 m2 = *(const float4*)&sIn[k][8];
        float4 m3 = *(const float4*)&sIn[k][12];
        acc0[0]=fmaf(m0.x,w0,acc0[0]); acc0[1]=fmaf(m0.y,w0,acc0[1]);
        acc0[2]=fmaf(m0.z,w0,acc0[2]); acc0[3]=fmaf(m0.w,w0,acc0[3]);
        acc0[4]=fmaf(m1.x,w0,acc0[4]); acc0[5]=fmaf(m1.y,w0,acc0[5]);
        acc0[6]=fmaf(m1.z,w0,acc0[6]); acc0[7]=fmaf(m1.w,w0,acc0[7]);
        acc0[8]=fmaf(m2.x,w0,acc0[8]); acc0[9]=fmaf(m2.y,w0,acc0[9]);
        acc0[10]=fmaf(m2.z,w0,acc0[10]); acc0[11]=fmaf(m2.w,w0,acc0[11]);
        acc0[12]=fmaf(m3.x,w0,acc0[12]); acc0[13]=fmaf(m3.y,w0,acc0[13]);
        acc0[14]=fmaf(m3.z,w0,acc0[14]); acc0[15]=fmaf(m3.w,w0,acc0[15]);
        acc1[0]=fmaf(m0.x,w1,acc1[0]); acc1[1]=fmaf(m0.y,w1,acc1[1]);
        acc1[2]=fmaf(m0.z,w1,acc1[2]); acc1[3]=fmaf(m0.w,w1,acc1[3]);
        acc1[4]=fmaf(m1.x,w1,acc1[4]); acc1[5]=fmaf(m1.y,w1,acc1[5]);
        acc1[6]=fmaf(m1.z,w1,acc1[6]); acc1[7]=fmaf(m1.w,w1,acc1[7]);
        acc1[8]=fmaf(m2.x,w1,acc1[8]); acc1[9]=fmaf(m2.y,w1,acc1[9]);
        acc1[10]=fmaf(m2.z,w1,acc1[10]); acc1[11]=fmaf(m2.w,w1,acc1[11]);
        acc1[12]=fmaf(m3.x,w1,acc1[12]); acc1[13]=fmaf(m3.y,w1,acc1[13]);
        acc1[14]=fmaf(m3.z,w1,acc1[14]); acc1[15]=fmaf(m3.w,w1,acc1[15]);
    }
    float b0 = bias[j0], b1 = bias[j1];
#pragma unroll
    for (int r = 0; r < 16; r++) {
        size_t base = (size_t)(row0 + r) * G4H;
        g_xproj[base + j0] = acc0[r] + b0;
        g_xproj[base + j1] = acc1[r] + b1;
    }
}

// ---------------- SLSTM scan step -------------------------------------------
// grid = 128 blocks = 64 row-tiles(16 rows) x 2 h-halves(64 h each), 256 thr
// LAYER==1 writes spikes; LAYER==2 accumulates mem into g_memsum.
template<int LAYER>
__global__ void __launch_bounds__(256) scan_step(int t, const float* __restrict__ thr_p) {
    __shared__ float sMemT[H][20];     // padded: 16B-aligned rows, fewer ph2 conflicts
    __shared__ float sG[16][256];
    const float* __restrict__ wT    = (LAYER == 1) ? g_whh1T : g_whh2T;
    const float* __restrict__ memIn = (t & 1) ? g_memB : g_memA;
    float* __restrict__ memOut      = (t & 1) ? g_memA : g_memB;
    int tid = threadIdx.x;
    int row0 = (blockIdx.x >> 1) << 4;
    int h0   = (blockIdx.x & 1) << 6;

    for (int idx = tid; idx < 16 * H; idx += 256) {
        int r = idx >> 7, k = idx & 127;
        sMemT[k][r] = memIn[(row0 + r) * H + k];
    }
    __syncthreads();

    int gate = tid >> 6;
    int hh = tid & 63;
    int col = (gate << 7) + h0 + hh;   // gate*128 + h
    float acc[16];
#pragma unroll
    for (int r = 0; r < 16; r++) acc[r] = 0.f;
#pragma unroll 8
    for (int k = 0; k < H; k++) {
        float w = wT[k * G4H + col];
        float4 m0 = *(const float4*)&sMemT[k][0];
        float4 m1 = *(const float4*)&sMemT[k][4];
        float4 m2 = *(const float4*)&sMemT[k][8];
        float4 m3 = *(const float4*)&sMemT[k][12];
        acc[0]=fmaf(m0.x,w,acc[0]);  acc[1]=fmaf(m0.y,w,acc[1]);
        acc[2]=fmaf(m0.z,w,acc[2]);  acc[3]=fmaf(m0.w,w,acc[3]);
        acc[4]=fmaf(m1.x,w,acc[4]);  acc[5]=fmaf(m1.y,w,acc[5]);
        acc[6]=fmaf(m1.z,w,acc[6]);  acc[7]=fmaf(m1.w,w,acc[7]);
        acc[8]=fmaf(m2.x,w,acc[8]);  acc[9]=fmaf(m2.y,w,acc[9]);
        acc[10]=fmaf(m2.z,w,acc[10]); acc[11]=fmaf(m2.w,w,acc[11]);
        acc[12]=fmaf(m3.x,w,acc[12]); acc[13]=fmaf(m3.y,w,acc[13]);
        acc[14]=fmaf(m3.z,w,acc[14]); acc[15]=fmaf(m3.w,w,acc[15]);
    }
    const float* xp = g_xproj + ((size_t)t * LLEN + row0) * G4H + col;
#pragma unroll
    for (int r = 0; r < 16; r++) sG[r][tid] = acc[r] + xp[(size_t)r * G4H];
    __syncthreads();

    float thr = *thr_p;
#pragma unroll
    for (int s = 0; s < 4; s++) {
        int idx = tid + (s << 8);
        int r = idx >> 6;
        int hl = idx & 63;
        float iv = sG[r][hl];
        float fv = sG[r][64 + hl];
        float gv = sG[r][128 + hl];
        float ov = sG[r][192 + hl];
        int h = h0 + hl;
        int gidx = (row0 + r) * H + h;
        float syn_old = g_synA[gidx];
        float mem_old = sMemT[h][r];
        float reset = (mem_old - thr) > 0.f ? thr : 0.f;
        float si = 1.f / (1.f + expf(-iv));
        float sf = 1.f / (1.f + expf(-fv));
        float so = 1.f / (1.f + expf(-ov));
        float syn_n = sf * syn_old + si * tanhf(gv);
        float mem_n = so * tanhf(syn_n) - reset;
        g_synA[gidx] = syn_n;
        memOut[gidx] = mem_n;
        if (LAYER == 1)
            g_spk1[(size_t)t * LLEN * H + gidx] = (mem_n - thr) > 0.f ? 1.f : 0.f;
        else
            g_memsum[gidx] += mem_n;
    }
}

// ---------------- BN stats: per-channel spike sums (deterministic) ----------
__global__ void __launch_bounds__(256) bn_stats() {
    __shared__ float sp[256];
    int tid = threadIdx.x;
    int h = tid & 127;
    int half = tid >> 7;
    float s = 0.f;
    size_t base = (size_t)blockIdx.x * 1024 * H;
    for (int rr = half; rr < 1024; rr += 2)
        s += g_spk1[base + (size_t)rr * H + h];
    sp[tid] = s;
    __syncthreads();
    if (tid < 128) g_part[blockIdx.x * H + tid] = sp[tid] + sp[tid + 128];
}

// ---------------- fold BN into layer-2 input weights -------------------------
__global__ void prep2(const float* __restrict__ w_ih2, const float* __restrict__ b_ih2,
                      const float* __restrict__ b_hh2, const float* __restrict__ gamma,
                      const float* __restrict__ beta) {
    __shared__ float sa[H], sbv[H];
    int tid = threadIdx.x;
    if (tid < H) {
        float sum = 0.f;
        for (int b = 0; b < 256; b++) sum += g_part[b * H + tid];
        float mu = sum / (float)M_TOT;
        float var = mu - mu * mu;            // binary data: E[x^2] = E[x]
        float a = gamma[tid] * rsqrtf(var + 1e-5f);
        sa[tid] = a;
        sbv[tid] = beta[tid] - mu * a;
    }
    __syncthreads();
    if (tid < G4H) {
        float bias = b_ih2[tid] + b_hh2[tid];
        for (int k = 0; k < H; k++) {
            float w = w_ih2[tid * H + k];
            g_awT[k * G4H + tid] = sa[k] * w;
            bias = fmaf(sbv[k], w, bias);
        }
        g_bias2[tid] = bias;
    }
}

// ---------------- final FC --------------------------------------------------
__global__ void fc_kernel(const float* __restrict__ fc_w, const float* __restrict__ fc_b,
                          float* __restrict__ out) {
    int gid = blockIdx.x * blockDim.x + threadIdx.x;
    if (gid >= LLEN * NC) return;
    int l = gid / NC, n = gid % NC;
    float s = 0.f;
#pragma unroll 8
    for (int h = 0; h < H; h++) s = fmaf(g_memsum[l * H + h], fc_w[n * H + h], s);
    out[gid] = s * (1.0f / 256.0f) + fc_b[n];
}

// ---------------- launch ----------------------------------------------------
extern "C" void kernel_launch(void* const* d_in, const int* in_sizes, int n_in,
                              void* d_out, int out_size) {
    const float* x      = (const float*)d_in[0];
    const float* conv_w = (const float*)d_in[1];
    const float* conv_b = (const float*)d_in[2];
    const float* w_ih1  = (const float*)d_in[3];
    const float* w_hh1  = (const float*)d_in[4];
    const float* b_ih1  = (const float*)d_in[5];
    const float* b_hh1  = (const float*)d_in[6];
    const float* thr1   = (const float*)d_in[7];
    const float* w_ih2  = (const float*)d_in[8];
    const float* w_hh2  = (const float*)d_in[9];
    const float* b_ih2  = (const float*)d_in[10];
    const float* b_hh2  = (const float*)d_in[11];
    const float* thr2   = (const float*)d_in[12];
    const float* gamma  = (const float*)d_in[13];
    const float* beta   = (const float*)d_in[14];
    const float* fc_w   = (const float*)d_in[15];
    const float* fc_b   = (const float*)d_in[16];
    float* out = (float*)d_out;

    prep0<<<128, 256>>>(w_ih1, w_hh1, b_ih1, b_hh1, w_hh2);
    zero_state<<<512, 256>>>();
    conv_spike<<<M_TOT / 256, 256>>>(x, conv_w, conv_b);
    gemm_xproj<32, 0><<<M_TOT / 16, 256>>>();

    for (int t = 0; t < T_STEPS; t++)
        scan_step<1><<<128, 256>>>(t, thr1);

    bn_stats<<<256, 256>>>();
    prep2<<<1, 512>>>(w_ih2, b_ih2, b_hh2, gamma, beta);
    gemm_xproj<128, 1><<<M_TOT / 16, 256>>>();

    zero_state<<<512, 256>>>();
    for (int t = 0; t < T_STEPS; t++)
        scan_step<2><<<128, 256>>>(t, thr2);

    fc_kernel<<<(LLEN * NC + 255) / 256, 256>>>(fc_w, fc_b, out);
}

// round 3
// speedup vs baseline: 1.5517x; 1.5517x over previous
#include <cuda_runtime.h>
#include <math.h>

#define T_STEPS 256
#define LLEN    1024
#define CIN     14
#define CCONV   32
#define H       128
#define G4H     512
#define NC      7
#define M_TOT   (T_STEPS*LLEN)   // 262144

// ---------------- scratch (device globals; allocation is banned) ----------
__device__ float g_cur1[(size_t)M_TOT * CCONV];   //  32 MB  conv spikes [row, 32]
__device__ float g_spk1[(size_t)M_TOT * H];       // 128 MB  layer-1 spikes [row, H]
__device__ float g_memsum[LLEN * H];
__device__ float g_part[256 * H];                 // BN partial sums
__device__ float g_wc1T[(CCONV + H) * G4H];       // [k][j]: rows 0..31 w_ih1T, 32..159 w_hh1T
__device__ float g_wc2T[(H + H) * G4H];           // [k][j]: rows 0..127 BN-scaled w_ih2T, 128..255 w_hh2T
__device__ float g_bias1[G4H];                    // b_ih1 + b_hh1
__device__ float g_bias2[G4H];                    // b_ih2 + b_hh2 + BN-shift folded
__device__ float g_sa[H];                         // BN scale
__device__ float g_sbv[H];                        // BN shift

// ---------------- prep: static weight transposes + bias combine ------------
__global__ void prep0(const float* __restrict__ w_ih1, const float* __restrict__ w_hh1,
                      const float* __restrict__ b_ih1, const float* __restrict__ b_hh1,
                      const float* __restrict__ w_hh2) {
    int stride = gridDim.x * blockDim.x;
    int i0 = blockIdx.x * blockDim.x + threadIdx.x;
    // wc1T: combined [32 conv ; 128 mem] x 512
    for (int idx = i0; idx < (CCONV + H) * G4H; idx += stride) {
        int k = idx / G4H, j = idx % G4H;
        g_wc1T[idx] = (k < CCONV) ? w_ih1[j * CCONV + k] : w_hh1[j * H + (k - CCONV)];
    }
    // wc2T mem half (static); input half filled by prep2b after BN stats
    for (int idx = i0; idx < H * G4H; idx += stride) {
        int k = idx / G4H, j = idx % G4H;
        g_wc2T[(H + k) * G4H + j] = w_hh2[j * H + k];
    }
    for (int idx = i0; idx < G4H; idx += stride)
        g_bias1[idx] = b_ih1[idx] + b_hh1[idx];
}

// ---------------- conv1d(k=3,pad=1) + Leaky spike ---------------------------
__global__ void __launch_bounds__(256) conv_spike(const float* __restrict__ x,
                                                  const float* __restrict__ conv_w,
                                                  const float* __restrict__ conv_b) {
    __shared__ float sw[3][CIN][CCONV];
    __shared__ float sb[CCONV];
    int tid = threadIdx.x;
    for (int i = tid; i < 3 * CIN * CCONV; i += 256) {
        int c = i % CCONV; int rem = i / CCONV; int ci = rem % CIN; int kk = rem / CIN;
        sw[kk][ci][c] = conv_w[(c * CIN + ci) * 3 + kk];
    }
    if (tid < CCONV) sb[tid] = conv_b[tid];
    __syncthreads();

    int gid = blockIdx.x * 256 + tid;   // over M_TOT
    int t = gid >> 10, l = gid & 1023;
    float acc[CCONV];
#pragma unroll
    for (int c = 0; c < CCONV; c++) acc[c] = sb[c];
#pragma unroll
    for (int kk = 0; kk < 3; kk++) {
        int ll = l + kk - 1;
        bool valid = (ll >= 0 && ll < LLEN);
        const float* xp = x + ((size_t)t * LLEN + (valid ? ll : 0)) * CIN;
#pragma unroll
        for (int ci = 0; ci < CIN; ci++) {
            float xv = valid ? xp[ci] : 0.f;
#pragma unroll
            for (int c = 0; c < CCONV; c++) acc[c] = fmaf(xv, sw[kk][ci][c], acc[c]);
        }
    }
    float4* outp = (float4*)&g_cur1[(size_t)gid * CCONV];
#pragma unroll
    for (int q = 0; q < 8; q++) {
        float4 v;
        v.x = (acc[q*4+0] - 1.0f) > 0.f ? 1.f : 0.f;
        v.y = (acc[q*4+1] - 1.0f) > 0.f ? 1.f : 0.f;
        v.z = (acc[q*4+2] - 1.0f) > 0.f ? 1.f : 0.f;
        v.w = (acc[q*4+3] - 1.0f) > 0.f ? 1.f : 0.f;
        outp[q] = v;
    }
}

// ---------------- persistent fused SLSTM scan -------------------------------
// 128 blocks x 512 threads. Each block owns 8 rows for ALL 256 steps; rows are
// independent across the recurrence, so no inter-block sync is needed.
// gates = [input_t ; mem] @ wcT + bias, with input fused as extra K.
// State (mem, syn, memsum) lives in SMEM for the whole kernel.
template<int KIN, int LAYER>
__global__ void __launch_bounds__(512, 1) scan_all(const float* __restrict__ thr_p) {
    constexpr int KTOT = KIN + H;
    __shared__ float inT[KTOT][8];     // [k][r]: rows 0..KIN-1 input, KIN.. mem (transposed)
    __shared__ float sG[8][G4H];       // gate pre-activations
    __shared__ float ssyn[8 * H];
    __shared__ float msum[8 * H];

    const float* __restrict__ wT = (LAYER == 1) ? g_wc1T : g_wc2T;
    const float* __restrict__ bi = (LAYER == 1) ? g_bias1 : g_bias2;
    const int tid = threadIdx.x;       // = output col j, 0..511
    const int row0 = blockIdx.x * 8;
    const float thr = *thr_p;
    const float bias = bi[tid];
    const float* __restrict__ wp = wT + tid;

    // zero state
    for (int e = tid; e < 8 * H; e += 512) { ssyn[e] = 0.f; msum[e] = 0.f; }
    for (int e = tid; e < H * 8; e += 512) inT[KIN + (e >> 3)][e & 7] = 0.f;

    for (int t = 0; t < T_STEPS; t++) {
        // ---- load input tile (transposed into inT[0..KIN-1]) ----
        if (KIN == CCONV) {
            if (tid < 256) {
                int r = tid >> 5, k = tid & 31;
                inT[k][r] = g_cur1[((size_t)(t * LLEN + row0 + r)) * CCONV + k];
            }
        } else {
#pragma unroll
            for (int e = tid; e < 8 * H; e += 512) {
                int r = e >> 7, k = e & 127;
                inT[k][r] = g_spk1[((size_t)(t * LLEN + row0 + r)) * H + k];
            }
        }
        __syncthreads();   // input + mem writes visible before gemm

        // ---- gemm: acc[r] = sum_k inT[k][r] * w[k][j] ----
        float acc[8];
#pragma unroll
        for (int r = 0; r < 8; r++) acc[r] = 0.f;
#pragma unroll 8
        for (int k = 0; k < KTOT; k++) {
            float w = wp[k * G4H];
            float4 a = *(const float4*)&inT[k][0];
            float4 b = *(const float4*)&inT[k][4];
            acc[0] = fmaf(a.x, w, acc[0]);
            acc[1] = fmaf(a.y, w, acc[1]);
            acc[2] = fmaf(a.z, w, acc[2]);
            acc[3] = fmaf(a.w, w, acc[3]);
            acc[4] = fmaf(b.x, w, acc[4]);
            acc[5] = fmaf(b.y, w, acc[5]);
            acc[6] = fmaf(b.z, w, acc[6]);
            acc[7] = fmaf(b.w, w, acc[7]);
        }
#pragma unroll
        for (int r = 0; r < 8; r++) sG[r][tid] = acc[r] + bias;
        __syncthreads();   // gates visible; gemm reads of inT complete

        // ---- pointwise LSTM update (2 elements per thread) ----
#pragma unroll
        for (int s = 0; s < 2; s++) {
            int e = tid + (s << 9);
            int r = e >> 7, h = e & 127;
            float iv = sG[r][h];
            float fv = sG[r][H + h];
            float gv = sG[r][2 * H + h];
            float ov = sG[r][3 * H + h];
            float mem_old = inT[KIN + h][r];
            float reset = (mem_old - thr) > 0.f ? thr : 0.f;
            float si = 1.f / (1.f + expf(-iv));
            float sf = 1.f / (1.f + expf(-fv));
            float so = 1.f / (1.f + expf(-ov));
            float syn_n = sf * ssyn[e] + si * tanhf(gv);
            float mem_n = so * tanhf(syn_n) - reset;
            ssyn[e] = syn_n;
            inT[KIN + h][r] = mem_n;
            if (LAYER == 1)
                g_spk1[((size_t)(t * LLEN + row0 + r)) * H + h] =
                    (mem_n - thr) > 0.f ? 1.f : 0.f;
            else
                msum[e] += mem_n;
        }
        // no barrier needed here: next iter's input-STS touches a disjoint
        // smem region, and the barrier after input-STS orders mem writes.
    }

    if (LAYER == 2) {
        __syncthreads();
        for (int e = tid; e < 8 * H; e += 512) {
            int r = e >> 7, h = e & 127;
            g_memsum[(row0 + r) * H + h] = msum[e];
        }
    }
}

// ---------------- BN stats: per-channel spike sums (deterministic) ----------
__global__ void __launch_bounds__(256) bn_stats() {
    __shared__ float sp[256];
    int tid = threadIdx.x;
    int h = tid & 127;
    int half = tid >> 7;
    float s = 0.f;
    size_t base = (size_t)blockIdx.x * LLEN * H;
    for (int rr = half; rr < LLEN; rr += 2)
        s += g_spk1[base + (size_t)rr * H + h];
    sp[tid] = s;
    __syncthreads();
    if (tid < 128) g_part[blockIdx.x * H + tid] = sp[tid] + sp[tid + 128];
}

// ---------------- BN fold: scale/shift -> weights + bias --------------------
__global__ void prep2a(const float* __restrict__ gamma, const float* __restrict__ beta) {
    int h = threadIdx.x;   // 128 threads
    float sum = 0.f;
    for (int b = 0; b < 256; b++) sum += g_part[b * H + h];
    float mu = sum / (float)M_TOT;
    float var = mu - mu * mu;              // binary data: E[x^2] = E[x]
    float a = gamma[h] * rsqrtf(var + 1e-5f);
    g_sa[h] = a;
    g_sbv[h] = beta[h] - mu * a;
}

__global__ void prep2b(const float* __restrict__ w_ih2) {
    int k = blockIdx.x;    // 128 blocks
    int j = threadIdx.x;   // 512 threads
    g_wc2T[k * G4H + j] = g_sa[k] * w_ih2[j * H + k];
}

__global__ void prep2c(const float* __restrict__ w_ih2, const float* __restrict__ b_ih2,
                       const float* __restrict__ b_hh2) {
    int j = threadIdx.x;   // 512 threads
    float b = b_ih2[j] + b_hh2[j];
#pragma unroll 8
    for (int k = 0; k < H; k++) b = fmaf(g_sbv[k], w_ih2[j * H + k], b);
    g_bias2[j] = b;
}

// ---------------- final FC --------------------------------------------------
__global__ void fc_kernel(const float* __restrict__ fc_w, const float* __restrict__ fc_b,
                          float* __restrict__ out) {
    int gid = blockIdx.x * blockDim.x + threadIdx.x;
    if (gid >= LLEN * NC) return;
    int l = gid / NC, n = gid % NC;
    float s = 0.f;
#pragma unroll 8
    for (int h = 0; h < H; h++) s = fmaf(g_memsum[l * H + h], fc_w[n * H + h], s);
    out[gid] = s * (1.0f / 256.0f) + fc_b[n];
}

// ---------------- launch ----------------------------------------------------
extern "C" void kernel_launch(void* const* d_in, const int* in_sizes, int n_in,
                              void* d_out, int out_size) {
    const float* x      = (const float*)d_in[0];
    const float* conv_w = (const float*)d_in[1];
    const float* conv_b = (const float*)d_in[2];
    const float* w_ih1  = (const float*)d_in[3];
    const float* w_hh1  = (const float*)d_in[4];
    const float* b_ih1  = (const float*)d_in[5];
    const float* b_hh1  = (const float*)d_in[6];
    const float* thr1   = (const float*)d_in[7];
    const float* w_ih2  = (const float*)d_in[8];
    const float* w_hh2  = (const float*)d_in[9];
    const float* b_ih2  = (const float*)d_in[10];
    const float* b_hh2  = (const float*)d_in[11];
    const float* thr2   = (const float*)d_in[12];
    const float* gamma  = (const float*)d_in[13];
    const float* beta   = (const float*)d_in[14];
    const float* fc_w   = (const float*)d_in[15];
    const float* fc_b   = (const float*)d_in[16];
    float* out = (float*)d_out;

    prep0<<<128, 256>>>(w_ih1, w_hh1, b_ih1, b_hh1, w_hh2);
    conv_spike<<<M_TOT / 256, 256>>>(x, conv_w, conv_b);

    scan_all<CCONV, 1><<<128, 512>>>(thr1);   // layer 1: fused xproj + scan, persistent

    bn_stats<<<256, 256>>>();
    prep2a<<<1, 128>>>(gamma, beta);
    prep2b<<<128, 512>>>(w_ih2);
    prep2c<<<1, 512>>>(w_ih2, b_ih2, b_hh2);

    scan_all<H, 2><<<128, 512>>>(thr2);       // layer 2: fused BN + xproj + scan

    fc_kernel<<<(LLEN * NC + 255) / 256, 256>>>(fc_w, fc_b, out);
}

// round 4
// speedup vs baseline: 1.7406x; 1.1217x over previous
#include <cuda_runtime.h>
#include <math.h>

#define T_STEPS 256
#define LLEN    1024
#define CIN     14
#define CCONV   32
#define H       128
#define G4H     512
#define NC      7
#define M_TOT   (T_STEPS*LLEN)   // 262144

typedef unsigned long long u64;

// packed f32x2 helpers (sm_103a FFMA2 — only reachable via PTX)
__device__ __forceinline__ u64 pack2(float x) {
    u64 r; asm("mov.b64 %0, {%1, %1};" : "=l"(r) : "f"(x)); return r;
}
__device__ __forceinline__ void fma2(u64& d, u64 a, u64 b) {
    asm("fma.rn.f32x2 %0, %1, %2, %3;" : "=l"(d) : "l"(a), "l"(b), "l"(d));
}
__device__ __forceinline__ void unpack2(float& lo, float& hi, u64 v) {
    asm("mov.b64 {%0, %1}, %2;" : "=f"(lo), "=f"(hi) : "l"(v));
}

__device__ __forceinline__ float fsig(float x) {          // sigmoid
    return __fdividef(1.f, 1.f + __expf(-x));
}
__device__ __forceinline__ float ftanh(float x) {         // tanh, safe at +-inf
    float t = __expf(2.f * x);
    return 1.f - __fdividef(2.f, t + 1.f);
}

// ---------------- scratch (device globals; allocation is banned) ----------
__device__ float g_cur1[(size_t)M_TOT * CCONV];   //  32 MB  conv spikes [row, 32]
__device__ float g_spk1[(size_t)M_TOT * H];       // 128 MB  layer-1 spikes [row, H]
__device__ float g_memsum[LLEN * H];
__device__ float g_part[256 * H];                 // BN partial sums
__device__ float g_wc1T[(CCONV + H) * G4H];       // [k][j]: rows 0..31 w_ih1T, 32..159 w_hh1T
__device__ float g_wc2T[(H + H) * G4H];           // [k][j]: rows 0..127 BN-scaled w_ih2T, 128..255 w_hh2T
__device__ float g_bias1[G4H];                    // b_ih1 + b_hh1
__device__ float g_bias2[G4H];                    // b_ih2 + b_hh2 + BN-shift folded
__device__ float g_sa[H];                         // BN scale
__device__ float g_sbv[H];                        // BN shift

// ---------------- prep: static weight transposes + bias combine ------------
__global__ void prep0(const float* __restrict__ w_ih1, const float* __restrict__ w_hh1,
                      const float* __restrict__ b_ih1, const float* __restrict__ b_hh1,
                      const float* __restrict__ w_hh2) {
    int stride = gridDim.x * blockDim.x;
    int i0 = blockIdx.x * blockDim.x + threadIdx.x;
    for (int idx = i0; idx < (CCONV + H) * G4H; idx += stride) {
        int k = idx / G4H, j = idx % G4H;
        g_wc1T[idx] = (k < CCONV) ? w_ih1[j * CCONV + k] : w_hh1[j * H + (k - CCONV)];
    }
    for (int idx = i0; idx < H * G4H; idx += stride) {
        int k = idx / G4H, j = idx % G4H;
        g_wc2T[(H + k) * G4H + j] = w_hh2[j * H + k];
    }
    for (int idx = i0; idx < G4H; idx += stride)
        g_bias1[idx] = b_ih1[idx] + b_hh1[idx];
}

// ---------------- conv1d(k=3,pad=1) + Leaky spike ---------------------------
__global__ void __launch_bounds__(256) conv_spike(const float* __restrict__ x,
                                                  const float* __restrict__ conv_w,
                                                  const float* __restrict__ conv_b) {
    __shared__ float sw[3][CIN][CCONV];
    __shared__ float sb[CCONV];
    int tid = threadIdx.x;
    for (int i = tid; i < 3 * CIN * CCONV; i += 256) {
        int c = i % CCONV; int rem = i / CCONV; int ci = rem % CIN; int kk = rem / CIN;
        sw[kk][ci][c] = conv_w[(c * CIN + ci) * 3 + kk];
    }
    if (tid < CCONV) sb[tid] = conv_b[tid];
    __syncthreads();

    int gid = blockIdx.x * 256 + tid;   // over M_TOT
    int t = gid >> 10, l = gid & 1023;
    float acc[CCONV];
#pragma unroll
    for (int c = 0; c < CCONV; c++) acc[c] = sb[c];
#pragma unroll
    for (int kk = 0; kk < 3; kk++) {
        int ll = l + kk - 1;
        bool valid = (ll >= 0 && ll < LLEN);
        const float* xp = x + ((size_t)t * LLEN + (valid ? ll : 0)) * CIN;
#pragma unroll
        for (int ci = 0; ci < CIN; ci++) {
            float xv = valid ? xp[ci] : 0.f;
#pragma unroll
            for (int c = 0; c < CCONV; c++) acc[c] = fmaf(xv, sw[kk][ci][c], acc[c]);
        }
    }
    float4* outp = (float4*)&g_cur1[(size_t)gid * CCONV];
#pragma unroll
    for (int q = 0; q < 8; q++) {
        float4 v;
        v.x = (acc[q*4+0] - 1.0f) > 0.f ? 1.f : 0.f;
        v.y = (acc[q*4+1] - 1.0f) > 0.f ? 1.f : 0.f;
        v.z = (acc[q*4+2] - 1.0f) > 0.f ? 1.f : 0.f;
        v.w = (acc[q*4+3] - 1.0f) > 0.f ? 1.f : 0.f;
        outp[q] = v;
    }
}

// ---------------- persistent fused SLSTM scan -------------------------------
// 128 blocks x 512 threads. Each block owns 8 rows for ALL 256 steps; rows are
// independent across the recurrence, so no inter-block sync is needed.
// gates = [input_t ; mem] @ wcT + bias, with input fused as extra K.
// Inner loop uses packed fma.rn.f32x2 (2 rows per lane-pair).
template<int KIN, int LAYER>
__global__ void __launch_bounds__(512, 1) scan_all(const float* __restrict__ thr_p) {
    constexpr int KTOT = KIN + H;
    __shared__ __align__(16) float inT[KTOT][8];   // [k][r]: input rows then mem rows
    __shared__ float sG[8][G4H];                   // gate pre-activations
    __shared__ float ssyn[8 * H];
    __shared__ float msum[8 * H];

    const float* __restrict__ wT = (LAYER == 1) ? g_wc1T : g_wc2T;
    const float* __restrict__ bi = (LAYER == 1) ? g_bias1 : g_bias2;
    const int tid = threadIdx.x;       // = output col j, 0..511
    const int row0 = blockIdx.x * 8;
    const float thr = *thr_p;
    const float bias = bi[tid];
    const float* __restrict__ wp = wT + tid;

    for (int e = tid; e < 8 * H; e += 512) { ssyn[e] = 0.f; msum[e] = 0.f; }
    for (int e = tid; e < H * 8; e += 512) inT[KIN + (e >> 3)][e & 7] = 0.f;

    for (int t = 0; t < T_STEPS; t++) {
        // ---- load input tile (transposed into inT[0..KIN-1]) ----
        if (KIN == CCONV) {
            if (tid < 256) {
                int r = tid >> 5, k = tid & 31;
                inT[k][r] = g_cur1[((size_t)(t * LLEN + row0 + r)) * CCONV + k];
            }
        } else {
#pragma unroll
            for (int e = tid; e < 8 * H; e += 512) {
                int r = e >> 7, k = e & 127;
                inT[k][r] = g_spk1[((size_t)(t * LLEN + row0 + r)) * H + k];
            }
        }
        __syncthreads();   // input + mem writes visible before gemm

        // ---- gemm via FFMA2: acc pairs over 8 rows, one col per thread ----
        u64 acc0 = 0ull, acc1 = 0ull, acc2 = 0ull, acc3 = 0ull;
#pragma unroll 8
        for (int k = 0; k < KTOT; k++) {
            u64 w2 = pack2(wp[k * G4H]);
            ulonglong2 a = *(const ulonglong2*)&inT[k][0];
            ulonglong2 b = *(const ulonglong2*)&inT[k][4];
            fma2(acc0, a.x, w2);
            fma2(acc1, a.y, w2);
            fma2(acc2, b.x, w2);
            fma2(acc3, b.y, w2);
        }
        float g0, g1, g2, g3, g4, g5, g6, g7;
        unpack2(g0, g1, acc0);
        unpack2(g2, g3, acc1);
        unpack2(g4, g5, acc2);
        unpack2(g6, g7, acc3);
        sG[0][tid] = g0 + bias;  sG[1][tid] = g1 + bias;
        sG[2][tid] = g2 + bias;  sG[3][tid] = g3 + bias;
        sG[4][tid] = g4 + bias;  sG[5][tid] = g5 + bias;
        sG[6][tid] = g6 + bias;  sG[7][tid] = g7 + bias;
        __syncthreads();   // gates visible; gemm reads of inT complete

        // ---- pointwise LSTM update (2 elements per thread) ----
#pragma unroll
        for (int s = 0; s < 2; s++) {
            int e = tid + (s << 9);
            int r = e >> 7, h = e & 127;
            float iv = sG[r][h];
            float fv = sG[r][H + h];
            float gv = sG[r][2 * H + h];
            float ov = sG[r][3 * H + h];
            float mem_old = inT[KIN + h][r];
            float reset = (mem_old - thr) > 0.f ? thr : 0.f;
            float syn_n = fsig(fv) * ssyn[e] + fsig(iv) * ftanh(gv);
            float mem_n = fsig(ov) * ftanh(syn_n) - reset;
            ssyn[e] = syn_n;
            inT[KIN + h][r] = mem_n;
            if (LAYER == 1)
                g_spk1[((size_t)(t * LLEN + row0 + r)) * H + h] =
                    (mem_n - thr) > 0.f ? 1.f : 0.f;
            else
                msum[e] += mem_n;
        }
        // no barrier needed: next input-STS touches disjoint smem; the barrier
        // after input-STS orders the mem writes before the next gemm.
    }

    if (LAYER == 2) {
        __syncthreads();
        for (int e = tid; e < 8 * H; e += 512) {
            int r = e >> 7, h = e & 127;
            g_memsum[(row0 + r) * H + h] = msum[e];
        }
    }
}

// ---------------- BN stats: per-channel spike sums (deterministic) ----------
__global__ void __launch_bounds__(256) bn_stats() {
    __shared__ float sp[256];
    int tid = threadIdx.x;
    int h = tid & 127;
    int half = tid >> 7;
    float s = 0.f;
    size_t base = (size_t)blockIdx.x * LLEN * H;
    for (int rr = half; rr < LLEN; rr += 2)
        s += g_spk1[base + (size_t)rr * H + h];
    sp[tid] = s;
    __syncthreads();
    if (tid < 128) g_part[blockIdx.x * H + tid] = sp[tid] + sp[tid + 128];
}

// ---------------- BN fold: scale/shift -> weights + bias --------------------
__global__ void prep2a(const float* __restrict__ gamma, const float* __restrict__ beta) {
    int h = threadIdx.x;   // 128 threads
    float sum = 0.f;
    for (int b = 0; b < 256; b++) sum += g_part[b * H + h];
    float mu = sum / (float)M_TOT;
    float var = mu - mu * mu;              // binary data: E[x^2] = E[x]
    float a = gamma[h] * rsqrtf(var + 1e-5f);
    g_sa[h] = a;
    g_sbv[h] = beta[h] - mu * a;
}

__global__ void prep2b(const float* __restrict__ w_ih2) {
    int k = blockIdx.x;    // 128 blocks
    int j = threadIdx.x;   // 512 threads
    g_wc2T[k * G4H + j] = g_sa[k] * w_ih2[j * H + k];
}

__global__ void prep2c(const float* __restrict__ w_ih2, const float* __restrict__ b_ih2,
                       const float* __restrict__ b_hh2) {
    int j = threadIdx.x;   // 512 threads
    float b = b_ih2[j] + b_hh2[j];
#pragma unroll 8
    for (int k = 0; k < H; k++) b = fmaf(g_sbv[k], w_ih2[j * H + k], b);
    g_bias2[j] = b;
}

// ---------------- final FC --------------------------------------------------
__global__ void fc_kernel(const float* __restrict__ fc_w, const float* __restrict__ fc_b,
                          float* __restrict__ out) {
    int gid = blockIdx.x * blockDim.x + threadIdx.x;
    if (gid >= LLEN * NC) return;
    int l = gid / NC, n = gid % NC;
    float s = 0.f;
#pragma unroll 8
    for (int h = 0; h < H; h++) s = fmaf(g_memsum[l * H + h], fc_w[n * H + h], s);
    out[gid] = s * (1.0f / 256.0f) + fc_b[n];
}

// ---------------- launch ----------------------------------------------------
extern "C" void kernel_launch(void* const* d_in, const int* in_sizes, int n_in,
                              void* d_out, int out_size) {
    const float* x      = (const float*)d_in[0];
    const float* conv_w = (const float*)d_in[1];
    const float* conv_b = (const float*)d_in[2];
    const float* w_ih1  = (const float*)d_in[3];
    const float* w_hh1  = (const float*)d_in[4];
    const float* b_ih1  = (const float*)d_in[5];
    const float* b_hh1  = (const float*)d_in[6];
    const float* thr1   = (const float*)d_in[7];
    const float* w_ih2  = (const float*)d_in[8];
    const float* w_hh2  = (const float*)d_in[9];
    const float* b_ih2  = (const float*)d_in[10];
    const float* b_hh2  = (const float*)d_in[11];
    const float* thr2   = (const float*)d_in[12];
    const float* gamma  = (const float*)d_in[13];
    const float* beta   = (const float*)d_in[14];
    const float* fc_w   = (const float*)d_in[15];
    const float* fc_b   = (const float*)d_in[16];
    float* out = (float*)d_out;

    prep0<<<128, 256>>>(w_ih1, w_hh1, b_ih1, b_hh1, w_hh2);
    conv_spike<<<M_TOT / 256, 256>>>(x, conv_w, conv_b);

    scan_all<CCONV, 1><<<128, 512>>>(thr1);   // layer 1: fused xproj + scan

    bn_stats<<<256, 256>>>();
    prep2a<<<1, 128>>>(gamma, beta);
    prep2b<<<128, 512>>>(w_ih2);
    prep2c<<<1, 512>>>(w_ih2, b_ih2, b_hh2);

    scan_all<H, 2><<<128, 512>>>(thr2);       // layer 2: fused BN + xproj + scan

    fc_kernel<<<(LLEN * NC + 255) / 256, 256>>>(fc_w, fc_b, out);
}

// round 10
// speedup vs baseline: 2.0247x; 1.1632x over previous
#include <cuda_runtime.h>
#include <math.h>

#define T_STEPS 256
#define LLEN    1024
#define CIN     14
#define CCONV   32
#define H       128
#define G4H     512
#define NC      7
#define M_TOT   (T_STEPS*LLEN)   // 262144

typedef unsigned long long u64;
typedef unsigned int u32;

// packed f32x2 helpers (sm_103a FFMA2 — only reachable via PTX)
__device__ __forceinline__ u64 pack2(float x) {
    u64 r; asm("mov.b64 %0, {%1, %1};" : "=l"(r) : "f"(x)); return r;
}
__device__ __forceinline__ void fma2(u64& d, u64 a, u64 b) {
    asm("fma.rn.f32x2 %0, %1, %2, %3;" : "=l"(d) : "l"(a), "l"(b), "l"(d));
}
__device__ __forceinline__ void unpack2(float& lo, float& hi, u64 v) {
    asm("mov.b64 {%0, %1}, %2;" : "=f"(lo), "=f"(hi) : "l"(v));
}

__device__ __forceinline__ float fsig(float x) {          // sigmoid
    return __fdividef(1.f, 1.f + __expf(-x));
}
__device__ __forceinline__ float ftanh(float x) {         // tanh, safe at +-inf
    float t = __expf(2.f * x);
    return 1.f - __fdividef(2.f, t + 1.f);
}

// ---------------- scratch (device globals; allocation is banned) ----------
__device__ float g_cur1[(size_t)M_TOT * CCONV];   //  32 MB  conv spikes [row, 32]
__device__ float g_spk1[(size_t)M_TOT * H];       // 128 MB  layer-1 spikes [row, H]
__device__ float g_memsum[LLEN * H];
__device__ float g_part[256 * H];                 // BN partial sums
__device__ float g_wc1T[(CCONV + H) * G4H];       // fp32 [k][j]: 0..31 ih1, 32..159 hh1
__device__ float g_wc2T[(H + H) * G4H];           // fp32 [k][j]: 0..127 BN*ih2, 128..255 hh2
__device__ float g_bias1[G4H];                    // b_ih1 + b_hh1
__device__ float g_bias2[G4H];                    // b_ih2 + b_hh2 + BN-shift folded
__device__ float g_sa[H];                         // BN scale
__device__ float g_sbv[H];                        // BN shift

// ---------------- prep: static weight transposes + bias combine ------------
__global__ void prep0(const float* __restrict__ w_ih1, const float* __restrict__ w_hh1,
                      const float* __restrict__ b_ih1, const float* __restrict__ b_hh1,
                      const float* __restrict__ w_hh2) {
    int stride = gridDim.x * blockDim.x;
    int i0 = blockIdx.x * blockDim.x + threadIdx.x;
    for (int idx = i0; idx < (CCONV + H) * G4H; idx += stride) {
        int k = idx / G4H, j = idx % G4H;
        g_wc1T[idx] = (k < CCONV) ? w_ih1[j * CCONV + k] : w_hh1[j * H + (k - CCONV)];
    }
    for (int idx = i0; idx < H * G4H; idx += stride) {
        int k = idx / G4H, j = idx % G4H;
        g_wc2T[(H + k) * G4H + j] = w_hh2[j * H + k];
    }
    for (int idx = i0; idx < G4H; idx += stride)
        g_bias1[idx] = b_ih1[idx] + b_hh1[idx];
}

// ---------------- conv1d(k=3,pad=1) + Leaky spike ---------------------------
__global__ void __launch_bounds__(256) conv_spike(const float* __restrict__ x,
                                                  const float* __restrict__ conv_w,
                                                  const float* __restrict__ conv_b) {
    __shared__ float sw[3][CIN][CCONV];
    __shared__ float sb[CCONV];
    int tid = threadIdx.x;
    for (int i = tid; i < 3 * CIN * CCONV; i += 256) {
        int c = i % CCONV; int rem = i / CCONV; int ci = rem % CIN; int kk = rem / CIN;
        sw[kk][ci][c] = conv_w[(c * CIN + ci) * 3 + kk];
    }
    if (tid < CCONV) sb[tid] = conv_b[tid];
    __syncthreads();

    int gid = blockIdx.x * 256 + tid;   // over M_TOT
    int t = gid >> 10, l = gid & 1023;
    float acc[CCONV];
#pragma unroll
    for (int c = 0; c < CCONV; c++) acc[c] = sb[c];
#pragma unroll
    for (int kk = 0; kk < 3; kk++) {
        int ll = l + kk - 1;
        bool valid = (ll >= 0 && ll < LLEN);
        const float* xp = x + ((size_t)t * LLEN + (valid ? ll : 0)) * CIN;
#pragma unroll
        for (int ci = 0; ci < CIN; ci++) {
            float xv = valid ? xp[ci] : 0.f;
#pragma unroll
            for (int c = 0; c < CCONV; c++) acc[c] = fmaf(xv, sw[kk][ci][c], acc[c]);
        }
    }
    float4* outp = (float4*)&g_cur1[(size_t)gid * CCONV];
#pragma unroll
    for (int q = 0; q < 8; q++) {
        float4 v;
        v.x = (acc[q*4+0] - 1.0f) > 0.f ? 1.f : 0.f;
        v.y = (acc[q*4+1] - 1.0f) > 0.f ? 1.f : 0.f;
        v.z = (acc[q*4+2] - 1.0f) > 0.f ? 1.f : 0.f;
        v.w = (acc[q*4+3] - 1.0f) > 0.f ? 1.f : 0.f;
        outp[q] = v;
    }
}

// ---------------- persistent fused SLSTM scan -------------------------------
// 128 blocks x 256 threads; block owns 8 rows for ALL 256 steps (rows are
// independent across the recurrence). Thread owns 2 adjacent cols x 8 rows.
// First NCACHE k-rows of the fp32 weight matrix are cached in dynamic SMEM
// (reused all 256 steps); the rest stream from L2. FFMA2 fp32 accumulation.
template<int KIN, int LAYER, int NCACHE>
__global__ void __launch_bounds__(256, 1) scan_all(const float* __restrict__ thr_p) {
    constexpr int KTOT = KIN + H;
    extern __shared__ float dsm[];
    float* swc  = dsm;                     // NCACHE * G4H  cached weights
    float* inT8 = swc + NCACHE * G4H;      // KTOT * 8   [k][r] input rows then mem rows
    float* sG   = inT8 + KTOT * 8;         // 8 * G4H    gate pre-activations
    float* ssyn = sG + 8 * G4H;            // 8 * H
    float* msum = ssyn + 8 * H;            // 8 * H

    const float* __restrict__ wT = (LAYER == 1) ? g_wc1T : g_wc2T;
    const float* __restrict__ bi = (LAYER == 1) ? g_bias1 : g_bias2;
    const int tid = threadIdx.x;           // owns cols 2*tid, 2*tid+1
    const int row0 = blockIdx.x * 8;
    const float thr = *thr_p;
    const float2 bias = *(const float2*)&bi[2 * tid];

    // fill weight cache + zero state
    for (int e = tid; e < NCACHE * G4H; e += 256) swc[e] = wT[e];
    for (int e = tid; e < 8 * H; e += 256) { ssyn[e] = 0.f; msum[e] = 0.f; }
    for (int e = tid; e < H * 8; e += 256) inT8[(KIN + (e >> 3)) * 8 + (e & 7)] = 0.f;

    for (int t = 0; t < T_STEPS; t++) {
        // ---- load input tile (transposed into inT8[0..KIN-1]) ----
        if (KIN == CCONV) {
            int r = tid >> 5, k = tid & 31;
            inT8[k * 8 + r] = g_cur1[((size_t)(t * LLEN + row0 + r)) * CCONV + k];
        } else {
#pragma unroll
            for (int s = 0; s < 4; s++) {
                int e = tid + (s << 8);
                int r = e >> 7, k = e & 127;
                inT8[k * 8 + r] = g_spk1[((size_t)(t * LLEN + row0 + r)) * H + k];
            }
        }
        __syncthreads();   // covers cache/state init on t==0 too

        // ---- gemm via FFMA2: 2 cols x 4 row-pairs per thread ----
        u64 a00 = 0, a01 = 0, a02 = 0, a03 = 0;   // col 2*tid
        u64 a10 = 0, a11 = 0, a12 = 0, a13 = 0;   // col 2*tid+1
#pragma unroll 8
        for (int k = 0; k < NCACHE; k++) {         // cached weights (SMEM)
            float2 w = *(const float2*)&swc[k * G4H + 2 * tid];
            u64 w0 = pack2(w.x), w1 = pack2(w.y);
            ulonglong2 ra = *(const ulonglong2*)&inT8[k * 8];
            ulonglong2 rb = *(const ulonglong2*)&inT8[k * 8 + 4];
            fma2(a00, ra.x, w0); fma2(a01, ra.y, w0);
            fma2(a02, rb.x, w0); fma2(a03, rb.y, w0);
            fma2(a10, ra.x, w1); fma2(a11, ra.y, w1);
            fma2(a12, rb.x, w1); fma2(a13, rb.y, w1);
        }
#pragma unroll 8
        for (int k = NCACHE; k < KTOT; k++) {      // streamed weights (L2)
            float2 w = *(const float2*)&wT[(size_t)k * G4H + 2 * tid];
            u64 w0 = pack2(w.x), w1 = pack2(w.y);
            ulonglong2 ra = *(const ulonglong2*)&inT8[k * 8];
            ulonglong2 rb = *(const ulonglong2*)&inT8[k * 8 + 4];
            fma2(a00, ra.x, w0); fma2(a01, ra.y, w0);
            fma2(a02, rb.x, w0); fma2(a03, rb.y, w0);
            fma2(a10, ra.x, w1); fma2(a11, ra.y, w1);
            fma2(a12, rb.x, w1); fma2(a13, rb.y, w1);
        }
        {   // write gates: rows 2p, 2p+1 live in pair p
            u64 c0[4] = {a00, a01, a02, a03};
            u64 c1[4] = {a10, a11, a12, a13};
#pragma unroll
            for (int p = 0; p < 4; p++) {
                float lo0, hi0, lo1, hi1;
                unpack2(lo0, hi0, c0[p]);
                unpack2(lo1, hi1, c1[p]);
                float2 e0 = make_float2(lo0 + bias.x, lo1 + bias.y);
                float2 e1 = make_float2(hi0 + bias.x, hi1 + bias.y);
                *(float2*)&sG[(2 * p) * G4H + 2 * tid] = e0;
                *(float2*)&sG[(2 * p + 1) * G4H + 2 * tid] = e1;
            }
        }
        __syncthreads();   // gates visible; gemm reads of inT8 complete

        // ---- pointwise LSTM update (4 elements per thread) ----
#pragma unroll
        for (int s = 0; s < 4; s++) {
            int e = tid + (s << 8);
            int r = e >> 7, h = e & 127;
            float iv = sG[r * G4H + h];
            float fv = sG[r * G4H + H + h];
            float gv = sG[r * G4H + 2 * H + h];
            float ov = sG[r * G4H + 3 * H + h];
            float mem_old = inT8[(KIN + h) * 8 + r];
            float reset = (mem_old - thr) > 0.f ? thr : 0.f;
            float syn_n = fsig(fv) * ssyn[e] + fsig(iv) * ftanh(gv);
            float mem_n = fsig(ov) * ftanh(syn_n) - reset;
            ssyn[e] = syn_n;
            inT8[(KIN + h) * 8 + r] = mem_n;
            if (LAYER == 1)
                g_spk1[((size_t)(t * LLEN + row0 + r)) * H + h] =
                    (mem_n - thr) > 0.f ? 1.f : 0.f;
            else
                msum[e] += mem_n;
        }
        // no barrier needed: next input-STS touches disjoint smem; the barrier
        // after input-STS orders mem writes before the next gemm.
    }

    if (LAYER == 2) {
        __syncthreads();
        for (int e = tid; e < 8 * H; e += 256) {
            int r = e >> 7, h = e & 127;
            g_memsum[(row0 + r) * H + h] = msum[e];
        }
    }
}

// ---------------- BN stats: per-channel spike sums (deterministic) ----------
__global__ void __launch_bounds__(256) bn_stats() {
    __shared__ float sp[256];
    int tid = threadIdx.x;
    int h = tid & 127;
    int half = tid >> 7;
    float s = 0.f;
    size_t base = (size_t)blockIdx.x * LLEN * H;
    for (int rr = half; rr < LLEN; rr += 2)
        s += g_spk1[base + (size_t)rr * H + h];
    sp[tid] = s;
    __syncthreads();
    if (tid < 128) g_part[blockIdx.x * H + tid] = sp[tid] + sp[tid + 128];
}

// ---------------- BN fold: scale/shift -> weights + bias --------------------
__global__ void prep2a(const float* __restrict__ gamma, const float* __restrict__ beta) {
    int h = threadIdx.x;   // 128 threads
    float sum = 0.f;
    for (int b = 0; b < 256; b++) sum += g_part[b * H + h];
    float mu = sum / (float)M_TOT;
    float var = mu - mu * mu;              // binary data: E[x^2] = E[x]
    float a = gamma[h] * rsqrtf(var + 1e-5f);
    g_sa[h] = a;
    g_sbv[h] = beta[h] - mu * a;
}

__global__ void prep2b(const float* __restrict__ w_ih2) {
    int k = blockIdx.x;    // 128 blocks
    int j = threadIdx.x;   // 512 threads
    g_wc2T[k * G4H + j] = g_sa[k] * w_ih2[j * H + k];
}

__global__ void prep2c(const float* __restrict__ w_ih2, const float* __restrict__ b_ih2,
                       const float* __restrict__ b_hh2) {
    int j = threadIdx.x;   // 512 threads
    float b = b_ih2[j] + b_hh2[j];
#pragma unroll 8
    for (int k = 0; k < H; k++) b = fmaf(g_sbv[k], w_ih2[j * H + k], b);
    g_bias2[j] = b;
}

// ---------------- final FC --------------------------------------------------
__global__ void fc_kernel(const float* __restrict__ fc_w, const float* __restrict__ fc_b,
                          float* __restrict__ out) {
    int gid = blockIdx.x * blockDim.x + threadIdx.x;
    if (gid >= LLEN * NC) return;
    int l = gid / NC, n = gid % NC;
    float s = 0.f;
#pragma unroll 8
    for (int h = 0; h < H; h++) s = fmaf(g_memsum[l * H + h], fc_w[n * H + h], s);
    out[gid] = s * (1.0f / 256.0f) + fc_b[n];
}

// ---------------- launch ----------------------------------------------------
#define NCACHE1 96
#define NCACHE2 96

extern "C" void kernel_launch(void* const* d_in, const int* in_sizes, int n_in,
                              void* d_out, int out_size) {
    const float* x      = (const float*)d_in[0];
    const float* conv_w = (const float*)d_in[1];
    const float* conv_b = (const float*)d_in[2];
    const float* w_ih1  = (const float*)d_in[3];
    const float* w_hh1  = (const float*)d_in[4];
    const float* b_ih1  = (const float*)d_in[5];
    const float* b_hh1  = (const float*)d_in[6];
    const float* thr1   = (const float*)d_in[7];
    const float* w_ih2  = (const float*)d_in[8];
    const float* w_hh2  = (const float*)d_in[9];
    const float* b_ih2  = (const float*)d_in[10];
    const float* b_hh2  = (const float*)d_in[11];
    const float* thr2   = (const float*)d_in[12];
    const float* gamma  = (const float*)d_in[13];
    const float* beta   = (const float*)d_in[14];
    const float* fc_w   = (const float*)d_in[15];
    const float* fc_b   = (const float*)d_in[16];
    float* out = (float*)d_out;

    // dynamic smem sizes (bytes)
    const int smem1 = (NCACHE1 * G4H + (CCONV + H) * 8 + 8 * G4H + 16 * H) * 4;  // 226304
    const int smem2 = (NCACHE2 * G4H + (H + H) * 8 + 8 * G4H + 16 * H) * 4;      // 229376
    cudaFuncSetAttribute(scan_all<CCONV, 1, NCACHE1>,
                         cudaFuncAttributeMaxDynamicSharedMemorySize, smem1);
    cudaFuncSetAttribute(scan_all<H, 2, NCACHE2>,
                         cudaFuncAttributeMaxDynamicSharedMemorySize, smem2);

    prep0<<<128, 256>>>(w_ih1, w_hh1, b_ih1, b_hh1, w_hh2);
    conv_spike<<<M_TOT / 256, 256>>>(x, conv_w, conv_b);

    scan_all<CCONV, 1, NCACHE1><<<128, 256, smem1>>>(thr1);   // layer 1

    bn_stats<<<256, 256>>>();
    prep2a<<<1, 128>>>(gamma, beta);
    prep2b<<<128, 512>>>(w_ih2);
    prep2c<<<1, 512>>>(w_ih2, b_ih2, b_hh2);

    scan_all<H, 2, NCACHE2><<<128, 256, smem2>>>(thr2);       // layer 2

    fc_kernel<<<(LLEN * NC + 255) / 256, 256>>>(fc_w, fc_b, out);
}